// round 16
// baseline (speedup 1.0000x reference)
#include <cuda_runtime.h>

#define NN 50000
#define NE 1600000
#define NSCAN 49   // ceil(NN/1024)

// ---------------- scratch (static device globals; zero at load; invariants restored per call) ----------------
__device__ int   g_cnt[NN];
__device__ int   g_cursor[NN];
__device__ int   g_base[NN];
__device__ int   g_bsum[64];
__device__ int4  g_enid[NE];        // {edge id, src node, tgt node, pad}: one 16B scatter
__device__ float g_P[(size_t)NN * 32];
__device__ float g_s1[(size_t)NN * 32];
__device__ float g_s2[(size_t)NN * 32];
__device__ float g_s3[(size_t)NN * 32];
__device__ float g_s4[(size_t)NN * 32];
__device__ float g_outpre[(size_t)NN * 16];
__device__ float g_bnsum[16];
__device__ float g_bnsq[16];

// ---------------- P = x_t @ W1a[0:16,:] + b1a, fused with src histogram + BN-sum zeroing ----------------
__global__ void k_inithist(const float* __restrict__ x_t,
                           const float* __restrict__ W1a,
                           const float* __restrict__ b1a,
                           const int*   __restrict__ src) {
    int i = blockIdx.x * blockDim.x + threadIdx.x;
    if (i < 16) { g_bnsum[i] = 0.f; g_bnsq[i] = 0.f; }
    if (i < NE) atomicAdd(&g_cnt[src[i]], 1);            // g_cnt zero on entry
    if (i >= NN) return;

    float x[16];
    const float4* xp = reinterpret_cast<const float4*>(x_t + (size_t)i * 16);
    #pragma unroll
    for (int q = 0; q < 4; q++) {
        float4 v = xp[q];
        x[4*q] = v.x; x[4*q+1] = v.y; x[4*q+2] = v.z; x[4*q+3] = v.w;
    }
    float p[32];
    #pragma unroll
    for (int j = 0; j < 32; j++) p[j] = __ldg(&b1a[j]);
    #pragma unroll
    for (int k = 0; k < 16; k++) {
        float a = x[k];
        #pragma unroll
        for (int j = 0; j < 32; j++) p[j] += a * __ldg(&W1a[k * 32 + j]);
    }
    float4* pp = reinterpret_cast<float4*>(g_P + (size_t)i * 32);
    #pragma unroll
    for (int q = 0; q < 8; q++) pp[q] = make_float4(p[4*q], p[4*q+1], p[4*q+2], p[4*q+3]);
}

// ---------------- per-block exclusive scan of counts ----------------
__global__ void k_scan1() {
    __shared__ int sm[1024];
    int lt = threadIdx.x;
    int i = blockIdx.x * 1024 + lt;
    int v = (i < NN) ? g_cnt[i] : 0;
    sm[lt] = v;
    __syncthreads();
    #pragma unroll
    for (int off = 1; off < 1024; off <<= 1) {
        int x = (lt >= off) ? sm[lt - off] : 0;
        __syncthreads();
        sm[lt] += x;
        __syncthreads();
    }
    if (i < NN) g_base[i] = sm[lt] - v;        // exclusive within block
    if (lt == 1023) g_bsum[blockIdx.x] = sm[1023];
}

// ---------------- scatter with inline block-sum scan; also gathers tgt (coalesced) ----------------
__global__ void k_scatter(const int* __restrict__ src, const int* __restrict__ tgt) {
    __shared__ int sbs[NSCAN];
    if (threadIdx.x == 0) {
        int run = 0;
        #pragma unroll
        for (int t = 0; t < NSCAN; t++) { int v = g_bsum[t]; sbs[t] = run; run += v; }
    }
    __syncthreads();
    int e = blockIdx.x * blockDim.x + threadIdx.x;
    if (e < NE) {
        int s = src[e];
        int t = tgt[e];
        int slot = g_base[s] + sbs[s >> 10] + atomicAdd(&g_cursor[s], 1);
        g_enid[slot] = make_int4(e, s, t, 0);
    }
}

// ---------------- fused edge MLP + moments; coop gathers + feature-major epilogue ----------------
__global__ __launch_bounds__(128, 4) void k_edge(const float* __restrict__ edge_attr,
                                                 const float* __restrict__ W1a,
                                                 const float* __restrict__ W2a,
                                                 const float* __restrict__ b2a) {
    __shared__ __align__(16) float sW1[16 * 32];
    __shared__ __align__(16) float sW2[32 * 32];
    __shared__ __align__(16) float sb2[32];
    __shared__ __align__(16) float s_buf[256 * 36];   // P stage (stride36) / ea stage (stride20) / m tile (feat-major stride260)
    __shared__ __align__(16) int   s_nid[256];
    for (int idx = threadIdx.x; idx < 512;  idx += 128) sW1[idx] = W1a[512 + idx];
    for (int idx = threadIdx.x; idx < 1024; idx += 128) sW2[idx] = W2a[idx];
    if (threadIdx.x < 32) sb2[threadIdx.x] = b2a[threadIdx.x];

    int tid = threadIdx.x;
    int lane = tid & 31, w = tid >> 5;
    int i0 = blockIdx.x * 256 + tid;      // NE % 256 == 0: always valid
    int i1 = i0 + 128;
    int4 p0i = g_enid[i0], p1i = g_enid[i1];
    int e0 = p0i.x, e1 = p1i.x;
    int t0 = p0i.z, t1 = p1i.z;
    s_nid[tid]       = p0i.y;
    s_nid[tid + 128] = p1i.y;

    // ---- cooperative P gather: 4 edges per LDG.128 op (1 line per edge) ----
    {
        int a = lane & 3, s = lane >> 2;         // sector s in 0..7
        int sp = (s + a) & 7;                    // swizzled write sector (a == el&3)
        #pragma unroll
        for (int j = 0; j < 8; j++) {
            int srcl = 4 * j + a;
            int elA  = w * 32 + srcl;
            int tA = __shfl_sync(0xffffffffu, t0, srcl);
            float4 vA = *reinterpret_cast<const float4*>(g_P + (size_t)tA * 32 + s * 4);
            *reinterpret_cast<float4*>(s_buf + elA * 36 + sp * 4) = vA;
            int tB = __shfl_sync(0xffffffffu, t1, srcl);
            float4 vB = *reinterpret_cast<const float4*>(g_P + (size_t)tB * 32 + s * 4);
            *reinterpret_cast<float4*>(s_buf + (elA + 128) * 36 + sp * 4) = vB;
        }
    }
    __syncwarp();

    // ---- readback own P rows into h accumulators ----
    float h0[32], h1[32];
    {
        int a0 = tid & 3;                        // el&3 for rows tid and tid+128
        #pragma unroll
        for (int s = 0; s < 8; s++) {
            int sp = (s + a0) & 7;
            float4 vA = *reinterpret_cast<const float4*>(s_buf + tid * 36 + sp * 4);
            float4 vB = *reinterpret_cast<const float4*>(s_buf + (tid + 128) * 36 + sp * 4);
            h0[4*s] = vA.x; h0[4*s+1] = vA.y; h0[4*s+2] = vA.z; h0[4*s+3] = vA.w;
            h1[4*s] = vB.x; h1[4*s+1] = vB.y; h1[4*s+2] = vB.z; h1[4*s+3] = vB.w;
        }
    }
    __syncthreads();   // P region free; ea staging below overlaps other warps' P words

    // ---- cooperative ea gather: 8 edges per LDG.128 op ----
    {
        int a = lane & 7, s = lane >> 3;         // sector s in 0..3
        #pragma unroll
        for (int j = 0; j < 4; j++) {
            int srcl = 8 * j + a;
            int elA  = w * 32 + srcl;
            int eA = __shfl_sync(0xffffffffu, e0, srcl);
            float4 vA = *reinterpret_cast<const float4*>(edge_attr + (size_t)eA * 16 + s * 4);
            *reinterpret_cast<float4*>(s_buf + elA * 20 + s * 4) = vA;
            int eB = __shfl_sync(0xffffffffu, e1, srcl);
            float4 vB = *reinterpret_cast<const float4*>(edge_attr + (size_t)eB * 16 + s * 4);
            *reinterpret_cast<float4*>(s_buf + (elA + 128) * 20 + s * 4) = vB;
        }
    }
    __syncwarp();

    // ---- layer 1 (edge_attr part): ea from smem stage, weights broadcast from smem ----
    #pragma unroll
    for (int q = 0; q < 4; q++) {
        float4 v0 = *reinterpret_cast<const float4*>(s_buf + tid * 20 + q * 4);
        float4 v1 = *reinterpret_cast<const float4*>(s_buf + (tid + 128) * 20 + q * 4);
        float a40[4] = {v0.x, v0.y, v0.z, v0.w};
        float a41[4] = {v1.x, v1.y, v1.z, v1.w};
        #pragma unroll
        for (int kk = 0; kk < 4; kk++) {
            float a0 = a40[kk], a1 = a41[kk];
            const float4* Wr = reinterpret_cast<const float4*>(sW1 + (4*q + kk) * 32);
            #pragma unroll
            for (int qq = 0; qq < 8; qq++) {
                float4 ww = Wr[qq];
                h0[4*qq]   += a0 * ww.x; h0[4*qq+1] += a0 * ww.y;
                h0[4*qq+2] += a0 * ww.z; h0[4*qq+3] += a0 * ww.w;
                h1[4*qq]   += a1 * ww.x; h1[4*qq+1] += a1 * ww.y;
                h1[4*qq+2] += a1 * ww.z; h1[4*qq+3] += a1 * ww.w;
            }
        }
    }
    #pragma unroll
    for (int j = 0; j < 32; j++) {
        h0[j] = fmaxf(h0[j], 0.1f * h0[j]);
        h1[j] = fmaxf(h1[j], 0.1f * h1[j]);
    }
    __syncthreads();   // ea region consumed; feature-major m tile writes below reuse it

    // ---- layer 2 in two 16-output halves; m written FEATURE-MAJOR: tile[j][e], stride 260 ----
    #pragma unroll
    for (int half = 0; half < 2; half++) {
        float m0[16], m1[16];
        #pragma unroll
        for (int j = 0; j < 16; j++) { m0[j] = sb2[16*half + j]; m1[j] = m0[j]; }
        #pragma unroll
        for (int k = 0; k < 32; k++) {
            float a0 = h0[k], a1 = h1[k];
            const float4* Wr = reinterpret_cast<const float4*>(sW2 + k * 32 + 16 * half);
            #pragma unroll
            for (int q = 0; q < 4; q++) {
                float4 ww = Wr[q];
                m0[4*q]   += a0 * ww.x; m0[4*q+1] += a0 * ww.y;
                m0[4*q+2] += a0 * ww.z; m0[4*q+3] += a0 * ww.w;
                m1[4*q]   += a1 * ww.x; m1[4*q+1] += a1 * ww.y;
                m1[4*q+2] += a1 * ww.z; m1[4*q+3] += a1 * ww.w;
            }
        }
        #pragma unroll
        for (int j = 0; j < 16; j++) {
            s_buf[(16*half + j) * 260 + tid]       = m0[j];
            s_buf[(16*half + j) * 260 + tid + 128] = m1[j];
        }
    }
    __syncthreads();

    // ---- segmented moment reduction: feature-major, float4 m + int4 nid reads ----
    #pragma unroll
    for (int p = 0; p < 2; p++) {
        int task = tid + 128 * p;
        int j = task & 31, band = task >> 5;
        const float* mrow = s_buf + j * 260 + band * 32;
        const int4*  nidp = reinterpret_cast<const int4*>(s_nid + band * 32);
        float s1 = 0.f, s2 = 0.f, s3 = 0.f, s4 = 0.f;
        int cur = s_nid[band * 32];
        #pragma unroll
        for (int i4 = 0; i4 < 8; i4++) {
            int4   n4 = nidp[i4];
            float4 m4 = *reinterpret_cast<const float4*>(mrow + 4 * i4);
            int   nv[4] = {n4.x, n4.y, n4.z, n4.w};
            float mv4[4] = {m4.x, m4.y, m4.z, m4.w};
            #pragma unroll
            for (int m = 0; m < 4; m++) {
                int nid = nv[m];
                if (nid != cur) {
                    size_t o = (size_t)cur * 32 + j;
                    atomicAdd(&g_s1[o], s1); atomicAdd(&g_s2[o], s2);
                    atomicAdd(&g_s3[o], s3); atomicAdd(&g_s4[o], s4);
                    s1 = s2 = s3 = s4 = 0.f;
                    cur = nid;
                }
                float mv = mv4[m];
                float qv = mv * mv;
                s1 += mv; s2 += qv; s3 += qv * mv; s4 += qv * qv;
            }
        }
        size_t o = (size_t)cur * 32 + j;
        atomicAdd(&g_s1[o], s1); atomicAdd(&g_s2[o], s2);
        atomicAdd(&g_s3[o], s3); atomicAdd(&g_s4[o], s4);
    }
}

// ---------------- node MLP: 32-node tile, smem-staged weights, float4 a-loads ----------------
__global__ __launch_bounds__(256) void k_node_mlp(const float* __restrict__ x_s,
                                                  const float* __restrict__ u,
                                                  const float* __restrict__ W1b,
                                                  const float* __restrict__ b1b,
                                                  const float* __restrict__ W2b,
                                                  const float* __restrict__ b2b) {
    __shared__ float hc[32][160];   // inputs for GEMM1; reused as W2b stage for GEMM2
    __shared__ float h2s[32][164];  // W1b chunk stage during GEMM1; then h2 activations
    __shared__ float sbn[16], sbnq[16];

    int base = blockIdx.x * 32;
    int tid = threadIdx.x;

    for (int idx = tid; idx < 32 * 32; idx += 256) {
        int nn = idx >> 5, f = idx & 31;
        int v = base + nn;
        float mean = 0.f, sd = 0.f, skew = 0.f, kurt = 0.f;
        if (v < NN) {
            size_t o = (size_t)v * 32 + f;
            float s1 = g_s1[o], s2 = g_s2[o], s3 = g_s3[o], s4 = g_s4[o];
            int c = g_cnt[v];
            float denom = (c > 0) ? (float)c : 1.0f;
            mean = s1 / denom;
            float var = s2 / denom - mean * mean;
            var = fmaxf(var, 0.01f * var);
            sd = sqrtf(var + 1e-6f);
            float mean2 = mean * mean;
            float m3c = s3 - 3.f * mean * s2 + 3.f * mean2 * s1 - denom * mean2 * mean;
            float m4c = s4 - 4.f * mean * s3 + 6.f * mean2 * s2
                        - 4.f * mean2 * mean * s1 + denom * mean2 * mean2;
            float inv_sd = 1.f / sd;
            float inv_sd2 = inv_sd * inv_sd;
            skew = m3c * inv_sd2 * inv_sd / denom;
            kurt = m4c * inv_sd2 * inv_sd2 / denom;
        }
        hc[nn][16 + f]  = mean;
        hc[nn][48 + f]  = sd;
        hc[nn][80 + f]  = skew;
        hc[nn][112 + f] = kurt;
    }
    for (int idx = tid; idx < 32 * 16; idx += 256) {
        int nn = idx >> 4, c = idx & 15;
        int v = base + nn;
        hc[nn][c] = (v < NN) ? x_s[(size_t)v * 16 + c] : 0.f;
        hc[nn][144 + c] = __ldg(&u[c]);
    }
    if (tid < 16) { sbn[tid] = 0.f; sbnq[tid] = 0.f; }

    int tx = tid & 31, ty = tid >> 5;
    float acc[4][5];
    #pragma unroll
    for (int q = 0; q < 4; q++)
        #pragma unroll
        for (int r = 0; r < 5; r++) acc[q][r] = 0.f;

    // GEMM1 in 5 chunks of 32 k; W1b chunk staged in h2s; a-loads as float4 per 4-k group
    float* swp = &h2s[0][0];
    #pragma unroll
    for (int chunk = 0; chunk < 5; chunk++) {
        __syncthreads();   // previous chunk consumed (first iter: orders stats/hc writes too)
        {
            const float4* Wc = reinterpret_cast<const float4*>(W1b + chunk * 32 * 160);
            float4* s4p = reinterpret_cast<float4*>(swp);
            #pragma unroll
            for (int idx = tid; idx < 1280; idx += 256) s4p[idx] = Wc[idx];
        }
        __syncthreads();
        #pragma unroll
        for (int t = 0; t < 8; t++) {          // 4-k groups
            float4 a4[4];
            #pragma unroll
            for (int q = 0; q < 4; q++)
                a4[q] = *reinterpret_cast<const float4*>(&hc[ty + 8 * q][chunk * 32 + 4 * t]);
            float av[4][4];
            #pragma unroll
            for (int q = 0; q < 4; q++) {
                av[q][0] = a4[q].x; av[q][1] = a4[q].y;
                av[q][2] = a4[q].z; av[q][3] = a4[q].w;
            }
            #pragma unroll
            for (int m = 0; m < 4; m++) {
                int kk = 4 * t + m;
                float w[5];
                #pragma unroll
                for (int r = 0; r < 5; r++) w[r] = swp[kk * 160 + tx + 32 * r];
                #pragma unroll
                for (int q = 0; q < 4; q++)
                    #pragma unroll
                    for (int r = 0; r < 5; r++) acc[q][r] += av[q][m] * w[r];
            }
        }
    }
    __syncthreads();

    // write h2 into h2s; stage W2b into hc (dead now)
    #pragma unroll
    for (int q = 0; q < 4; q++)
        #pragma unroll
        for (int r = 0; r < 5; r++) {
            int jj = tx + 32 * r;
            float hv = acc[q][r] + __ldg(&b1b[jj]);
            h2s[ty + 8 * q][jj] = fmaxf(hv, 0.1f * hv);
        }
    {
        float* w2s = &hc[0][0];
        const float4* W2c = reinterpret_cast<const float4*>(W2b);
        float4* s4p = reinterpret_cast<float4*>(w2s);
        #pragma unroll
        for (int idx = tid; idx < 640; idx += 256) s4p[idx] = W2c[idx];
    }
    __syncthreads();

    const float* w2s = &hc[0][0];
    int o = tid & 15, nr = tid >> 4;
    #pragma unroll
    for (int half = 0; half < 2; half++) {
        int nn = nr + 16 * half;
        float s = __ldg(&b2b[o]);
        #pragma unroll 8
        for (int k = 0; k < 160; k++) s += h2s[nn][k] * w2s[k * 16 + o];
        int v = base + nn;
        if (v < NN) {
            g_outpre[(size_t)v * 16 + o] = s;
            atomicAdd(&sbn[o], s);
            atomicAdd(&sbnq[o], s * s);
        }
    }
    __syncthreads();
    if (tid < 16) {
        atomicAdd(&g_bnsum[tid], sbn[tid]);
        atomicAdd(&g_bnsq[tid], sbnq[tid]);
    }
}

// ---------------- BN finalize + apply + cleanup (merged; float4-vectorized zeroing) ----------------
__global__ void k_applyclean(const float* __restrict__ gamma,
                             const float* __restrict__ beta,
                             float* __restrict__ out) {
    int i = blockIdx.x * blockDim.x + threadIdx.x;
    if (i < NN * 16) {
        int o = i & 15;
        float mu = g_bnsum[o] * (1.0f / (float)NN);
        float var = g_bnsq[o] * (1.0f / (float)NN) - mu * mu;
        float rsig = rsqrtf(var + 1e-5f);
        out[i] = gamma[o] * (g_outpre[i] - mu) * rsig + beta[o];
    }
    if (i < NN * 8) {
        float4 z = make_float4(0.f, 0.f, 0.f, 0.f);
        reinterpret_cast<float4*>(g_s1)[i] = z;
        reinterpret_cast<float4*>(g_s2)[i] = z;
        reinterpret_cast<float4*>(g_s3)[i] = z;
        reinterpret_cast<float4*>(g_s4)[i] = z;
    }
    if (i < NN) { g_cnt[i] = 0; g_cursor[i] = 0; }
}

// ---------------- launch ----------------
extern "C" void kernel_launch(void* const* d_in, const int* in_sizes, int n_in,
                              void* d_out, int out_size) {
    const float* x_s       = (const float*)d_in[0];
    const float* x_t       = (const float*)d_in[1];
    const float* edge_attr = (const float*)d_in[2];
    const float* u         = (const float*)d_in[3];
    const float* W1a       = (const float*)d_in[4];
    const float* b1a       = (const float*)d_in[5];
    const float* W2a       = (const float*)d_in[6];
    const float* b2a       = (const float*)d_in[7];
    const float* W1b       = (const float*)d_in[8];
    const float* b1b       = (const float*)d_in[9];
    const float* W2b       = (const float*)d_in[10];
    const float* b2b       = (const float*)d_in[11];
    const float* gamma     = (const float*)d_in[12];
    const float* beta      = (const float*)d_in[13];
    const int*   ei        = (const int*)d_in[14];
    const int* src = ei;
    const int* tgt = ei + NE;
    float* out = (float*)d_out;

    k_inithist <<<(NE + 255) / 256, 256>>>(x_t, W1a, b1a, src);       // #1
    k_scan1    <<<NSCAN, 1024>>>();                                   // #2
    k_scatter  <<<(NE + 255) / 256, 256>>>(src, tgt);                 // #3
    k_edge     <<<NE / 256, 128>>>(edge_attr, W1a, W2a, b2a);         // #4 <- profiled slot
    k_node_mlp <<<(NN + 31) / 32, 256>>>(x_s, u, W1b, b1b, W2b, b2b); // #5
    k_applyclean<<<(NN * 16 + 255) / 256, 256>>>(gamma, beta, out);   // #6
}

// round 17
// speedup vs baseline: 1.0492x; 1.0492x over previous
#include <cuda_runtime.h>

#define NN 50000
#define NE 1600000
#define NSCAN 49   // ceil(NN/1024)

// ---------------- scratch (static device globals; zero at load; invariants restored per call) ----------------
__device__ int   g_cnt[NN];
__device__ int   g_cursor[NN];
__device__ int   g_base[NN];
__device__ int   g_bsum[64];
__device__ int4  g_enid[NE];        // {edge id, src node, tgt node, pad}: one 16B scatter
__device__ float g_P[(size_t)NN * 32];
__device__ float g_s1[(size_t)NN * 32];
__device__ float g_s2[(size_t)NN * 32];
__device__ float g_s3[(size_t)NN * 32];
__device__ float g_s4[(size_t)NN * 32];
__device__ float g_outpre[(size_t)NN * 16];
__device__ float g_bnsum[16];
__device__ float g_bnsq[16];

// ---------------- P = x_t @ W1a[0:16,:] + b1a, fused with src histogram + BN-sum zeroing ----------------
__global__ void k_inithist(const float* __restrict__ x_t,
                           const float* __restrict__ W1a,
                           const float* __restrict__ b1a,
                           const int*   __restrict__ src) {
    int i = blockIdx.x * blockDim.x + threadIdx.x;
    if (i < 16) { g_bnsum[i] = 0.f; g_bnsq[i] = 0.f; }
    if (i < NE) atomicAdd(&g_cnt[src[i]], 1);            // g_cnt zero on entry
    if (i >= NN) return;

    float x[16];
    const float4* xp = reinterpret_cast<const float4*>(x_t + (size_t)i * 16);
    #pragma unroll
    for (int q = 0; q < 4; q++) {
        float4 v = xp[q];
        x[4*q] = v.x; x[4*q+1] = v.y; x[4*q+2] = v.z; x[4*q+3] = v.w;
    }
    float p[32];
    #pragma unroll
    for (int j = 0; j < 32; j++) p[j] = __ldg(&b1a[j]);
    #pragma unroll
    for (int k = 0; k < 16; k++) {
        float a = x[k];
        #pragma unroll
        for (int j = 0; j < 32; j++) p[j] += a * __ldg(&W1a[k * 32 + j]);
    }
    float4* pp = reinterpret_cast<float4*>(g_P + (size_t)i * 32);
    #pragma unroll
    for (int q = 0; q < 8; q++) pp[q] = make_float4(p[4*q], p[4*q+1], p[4*q+2], p[4*q+3]);
}

// ---------------- per-block exclusive scan of counts ----------------
__global__ void k_scan1() {
    __shared__ int sm[1024];
    int lt = threadIdx.x;
    int i = blockIdx.x * 1024 + lt;
    int v = (i < NN) ? g_cnt[i] : 0;
    sm[lt] = v;
    __syncthreads();
    #pragma unroll
    for (int off = 1; off < 1024; off <<= 1) {
        int x = (lt >= off) ? sm[lt - off] : 0;
        __syncthreads();
        sm[lt] += x;
        __syncthreads();
    }
    if (i < NN) g_base[i] = sm[lt] - v;        // exclusive within block
    if (lt == 1023) g_bsum[blockIdx.x] = sm[1023];
}

// ---------------- scatter with inline block-sum scan; also gathers tgt (coalesced) ----------------
__global__ void k_scatter(const int* __restrict__ src, const int* __restrict__ tgt) {
    __shared__ int sbs[NSCAN];
    if (threadIdx.x == 0) {
        int run = 0;
        #pragma unroll
        for (int t = 0; t < NSCAN; t++) { int v = g_bsum[t]; sbs[t] = run; run += v; }
    }
    __syncthreads();
    int e = blockIdx.x * blockDim.x + threadIdx.x;
    if (e < NE) {
        int s = src[e];
        int t = tgt[e];
        int slot = g_base[s] + sbs[s >> 10] + atomicAdd(&g_cursor[s], 1);
        g_enid[slot] = make_int4(e, s, t, 0);
    }
}

// ---------------- fused edge MLP + moments; cooperative line-granular gathers (R13 proven) ----------------
__global__ __launch_bounds__(128, 4) void k_edge(const float* __restrict__ edge_attr,
                                                 const float* __restrict__ W1a,
                                                 const float* __restrict__ W2a,
                                                 const float* __restrict__ b2a) {
    __shared__ __align__(16) float sW1[16 * 32];
    __shared__ __align__(16) float sW2[32 * 32];
    __shared__ __align__(16) float sb2[32];
    __shared__ __align__(16) float s_buf[256 * 36];   // P stage (stride36) / ea stage (stride20) / m tile (stride33)
    __shared__ int   s_nid[256];
    for (int idx = threadIdx.x; idx < 512;  idx += 128) sW1[idx] = W1a[512 + idx];
    for (int idx = threadIdx.x; idx < 1024; idx += 128) sW2[idx] = W2a[idx];
    if (threadIdx.x < 32) sb2[threadIdx.x] = b2a[threadIdx.x];

    int tid = threadIdx.x;
    int lane = tid & 31, w = tid >> 5;
    int i0 = blockIdx.x * 256 + tid;      // NE % 256 == 0: always valid
    int i1 = i0 + 128;
    int4 p0i = g_enid[i0], p1i = g_enid[i1];
    int e0 = p0i.x, e1 = p1i.x;
    int t0 = p0i.z, t1 = p1i.z;
    s_nid[tid]       = p0i.y;
    s_nid[tid + 128] = p1i.y;

    // ---- cooperative P gather: 4 edges per LDG.128 op (1 line per edge) ----
    {
        int a = lane & 3, s = lane >> 2;         // sector s in 0..7
        int sp = (s + a) & 7;                    // swizzled write sector (a == el&3)
        #pragma unroll
        for (int j = 0; j < 8; j++) {
            int srcl = 4 * j + a;
            int elA  = w * 32 + srcl;
            int tA = __shfl_sync(0xffffffffu, t0, srcl);
            float4 vA = *reinterpret_cast<const float4*>(g_P + (size_t)tA * 32 + s * 4);
            *reinterpret_cast<float4*>(s_buf + elA * 36 + sp * 4) = vA;
            int tB = __shfl_sync(0xffffffffu, t1, srcl);
            float4 vB = *reinterpret_cast<const float4*>(g_P + (size_t)tB * 32 + s * 4);
            *reinterpret_cast<float4*>(s_buf + (elA + 128) * 36 + sp * 4) = vB;
        }
    }
    __syncwarp();

    // ---- readback own P rows into h accumulators ----
    float h0[32], h1[32];
    {
        int a0 = tid & 3;                        // el&3 for rows tid and tid+128
        #pragma unroll
        for (int s = 0; s < 8; s++) {
            int sp = (s + a0) & 7;
            float4 vA = *reinterpret_cast<const float4*>(s_buf + tid * 36 + sp * 4);
            float4 vB = *reinterpret_cast<const float4*>(s_buf + (tid + 128) * 36 + sp * 4);
            h0[4*s] = vA.x; h0[4*s+1] = vA.y; h0[4*s+2] = vA.z; h0[4*s+3] = vA.w;
            h1[4*s] = vB.x; h1[4*s+1] = vB.y; h1[4*s+2] = vB.z; h1[4*s+3] = vB.w;
        }
    }
    __syncthreads();   // P region free; ea staging below overlaps other warps' P words

    // ---- cooperative ea gather: 8 edges per LDG.128 op ----
    {
        int a = lane & 7, s = lane >> 3;         // sector s in 0..3
        #pragma unroll
        for (int j = 0; j < 4; j++) {
            int srcl = 8 * j + a;
            int elA  = w * 32 + srcl;
            int eA = __shfl_sync(0xffffffffu, e0, srcl);
            float4 vA = *reinterpret_cast<const float4*>(edge_attr + (size_t)eA * 16 + s * 4);
            *reinterpret_cast<float4*>(s_buf + elA * 20 + s * 4) = vA;
            int eB = __shfl_sync(0xffffffffu, e1, srcl);
            float4 vB = *reinterpret_cast<const float4*>(edge_attr + (size_t)eB * 16 + s * 4);
            *reinterpret_cast<float4*>(s_buf + (elA + 128) * 20 + s * 4) = vB;
        }
    }
    __syncwarp();

    // ---- layer 1 (edge_attr part): ea from smem stage, weights broadcast from smem ----
    #pragma unroll
    for (int q = 0; q < 4; q++) {
        float4 v0 = *reinterpret_cast<const float4*>(s_buf + tid * 20 + q * 4);
        float4 v1 = *reinterpret_cast<const float4*>(s_buf + (tid + 128) * 20 + q * 4);
        float a40[4] = {v0.x, v0.y, v0.z, v0.w};
        float a41[4] = {v1.x, v1.y, v1.z, v1.w};
        #pragma unroll
        for (int kk = 0; kk < 4; kk++) {
            float a0 = a40[kk], a1 = a41[kk];
            const float4* Wr = reinterpret_cast<const float4*>(sW1 + (4*q + kk) * 32);
            #pragma unroll
            for (int qq = 0; qq < 8; qq++) {
                float4 ww = Wr[qq];
                h0[4*qq]   += a0 * ww.x; h0[4*qq+1] += a0 * ww.y;
                h0[4*qq+2] += a0 * ww.z; h0[4*qq+3] += a0 * ww.w;
                h1[4*qq]   += a1 * ww.x; h1[4*qq+1] += a1 * ww.y;
                h1[4*qq+2] += a1 * ww.z; h1[4*qq+3] += a1 * ww.w;
            }
        }
    }
    #pragma unroll
    for (int j = 0; j < 32; j++) {
        h0[j] = fmaxf(h0[j], 0.1f * h0[j]);
        h1[j] = fmaxf(h1[j], 0.1f * h1[j]);
    }
    __syncthreads();   // ea region consumed; m-tile writes below overlap other warps' ea words

    // ---- layer 2 in two 16-output halves; m written to stride-33 tile ----
    #pragma unroll
    for (int half = 0; half < 2; half++) {
        float m0[16], m1[16];
        #pragma unroll
        for (int j = 0; j < 16; j++) { m0[j] = sb2[16*half + j]; m1[j] = m0[j]; }
        #pragma unroll
        for (int k = 0; k < 32; k++) {
            float a0 = h0[k], a1 = h1[k];
            const float4* Wr = reinterpret_cast<const float4*>(sW2 + k * 32 + 16 * half);
            #pragma unroll
            for (int q = 0; q < 4; q++) {
                float4 ww = Wr[q];
                m0[4*q]   += a0 * ww.x; m0[4*q+1] += a0 * ww.y;
                m0[4*q+2] += a0 * ww.z; m0[4*q+3] += a0 * ww.w;
                m1[4*q]   += a1 * ww.x; m1[4*q+1] += a1 * ww.y;
                m1[4*q+2] += a1 * ww.z; m1[4*q+3] += a1 * ww.w;
            }
        }
        #pragma unroll
        for (int j = 0; j < 16; j++) {
            s_buf[tid * 33 + 16*half + j]         = m0[j];
            s_buf[(tid + 128) * 33 + 16*half + j] = m1[j];
        }
    }
    __syncthreads();

    // ---- segmented moment reduction over 256 rows: 8 bands x 32 features, 2 tasks/thread ----
    #pragma unroll
    for (int p = 0; p < 2; p++) {
        int task = tid + 128 * p;
        int j = task & 31, band = task >> 5;
        int rbeg = band * 32;
        float s1 = 0.f, s2 = 0.f, s3 = 0.f, s4 = 0.f;
        int cur = s_nid[rbeg];
        #pragma unroll 4
        for (int r = rbeg; r < rbeg + 32; r++) {
            int nid = s_nid[r];
            if (nid != cur) {
                size_t o = (size_t)cur * 32 + j;
                atomicAdd(&g_s1[o], s1); atomicAdd(&g_s2[o], s2);
                atomicAdd(&g_s3[o], s3); atomicAdd(&g_s4[o], s4);
                s1 = s2 = s3 = s4 = 0.f;
                cur = nid;
            }
            float mv = s_buf[r * 33 + j];
            float qv = mv * mv;
            s1 += mv; s2 += qv; s3 += qv * mv; s4 += qv * qv;
        }
        size_t o = (size_t)cur * 32 + j;
        atomicAdd(&g_s1[o], s1); atomicAdd(&g_s2[o], s2);
        atomicAdd(&g_s3[o], s3); atomicAdd(&g_s4[o], s4);
    }
}

// ---------------- node MLP: 32-node tile, smem-staged weights, float4 a-loads (R16 kept) ----------------
__global__ __launch_bounds__(256) void k_node_mlp(const float* __restrict__ x_s,
                                                  const float* __restrict__ u,
                                                  const float* __restrict__ W1b,
                                                  const float* __restrict__ b1b,
                                                  const float* __restrict__ W2b,
                                                  const float* __restrict__ b2b) {
    __shared__ float hc[32][160];   // inputs for GEMM1; reused as W2b stage for GEMM2
    __shared__ float h2s[32][164];  // W1b chunk stage during GEMM1; then h2 activations
    __shared__ float sbn[16], sbnq[16];

    int base = blockIdx.x * 32;
    int tid = threadIdx.x;

    for (int idx = tid; idx < 32 * 32; idx += 256) {
        int nn = idx >> 5, f = idx & 31;
        int v = base + nn;
        float mean = 0.f, sd = 0.f, skew = 0.f, kurt = 0.f;
        if (v < NN) {
            size_t o = (size_t)v * 32 + f;
            float s1 = g_s1[o], s2 = g_s2[o], s3 = g_s3[o], s4 = g_s4[o];
            int c = g_cnt[v];
            float denom = (c > 0) ? (float)c : 1.0f;
            mean = s1 / denom;
            float var = s2 / denom - mean * mean;
            var = fmaxf(var, 0.01f * var);
            sd = sqrtf(var + 1e-6f);
            float mean2 = mean * mean;
            float m3c = s3 - 3.f * mean * s2 + 3.f * mean2 * s1 - denom * mean2 * mean;
            float m4c = s4 - 4.f * mean * s3 + 6.f * mean2 * s2
                        - 4.f * mean2 * mean * s1 + denom * mean2 * mean2;
            float inv_sd = 1.f / sd;
            float inv_sd2 = inv_sd * inv_sd;
            skew = m3c * inv_sd2 * inv_sd / denom;
            kurt = m4c * inv_sd2 * inv_sd2 / denom;
        }
        hc[nn][16 + f]  = mean;
        hc[nn][48 + f]  = sd;
        hc[nn][80 + f]  = skew;
        hc[nn][112 + f] = kurt;
    }
    for (int idx = tid; idx < 32 * 16; idx += 256) {
        int nn = idx >> 4, c = idx & 15;
        int v = base + nn;
        hc[nn][c] = (v < NN) ? x_s[(size_t)v * 16 + c] : 0.f;
        hc[nn][144 + c] = __ldg(&u[c]);
    }
    if (tid < 16) { sbn[tid] = 0.f; sbnq[tid] = 0.f; }

    int tx = tid & 31, ty = tid >> 5;
    float acc[4][5];
    #pragma unroll
    for (int q = 0; q < 4; q++)
        #pragma unroll
        for (int r = 0; r < 5; r++) acc[q][r] = 0.f;

    // GEMM1 in 5 chunks of 32 k; W1b chunk staged in h2s; a-loads as float4 per 4-k group
    float* swp = &h2s[0][0];
    #pragma unroll
    for (int chunk = 0; chunk < 5; chunk++) {
        __syncthreads();   // previous chunk consumed (first iter: orders stats/hc writes too)
        {
            const float4* Wc = reinterpret_cast<const float4*>(W1b + chunk * 32 * 160);
            float4* s4p = reinterpret_cast<float4*>(swp);
            #pragma unroll
            for (int idx = tid; idx < 1280; idx += 256) s4p[idx] = Wc[idx];
        }
        __syncthreads();
        #pragma unroll
        for (int t = 0; t < 8; t++) {          // 4-k groups
            float4 a4[4];
            #pragma unroll
            for (int q = 0; q < 4; q++)
                a4[q] = *reinterpret_cast<const float4*>(&hc[ty + 8 * q][chunk * 32 + 4 * t]);
            float av[4][4];
            #pragma unroll
            for (int q = 0; q < 4; q++) {
                av[q][0] = a4[q].x; av[q][1] = a4[q].y;
                av[q][2] = a4[q].z; av[q][3] = a4[q].w;
            }
            #pragma unroll
            for (int m = 0; m < 4; m++) {
                int kk = 4 * t + m;
                float w[5];
                #pragma unroll
                for (int r = 0; r < 5; r++) w[r] = swp[kk * 160 + tx + 32 * r];
                #pragma unroll
                for (int q = 0; q < 4; q++)
                    #pragma unroll
                    for (int r = 0; r < 5; r++) acc[q][r] += av[q][m] * w[r];
            }
        }
    }
    __syncthreads();

    // write h2 into h2s; stage W2b into hc (dead now)
    #pragma unroll
    for (int q = 0; q < 4; q++)
        #pragma unroll
        for (int r = 0; r < 5; r++) {
            int jj = tx + 32 * r;
            float hv = acc[q][r] + __ldg(&b1b[jj]);
            h2s[ty + 8 * q][jj] = fmaxf(hv, 0.1f * hv);
        }
    {
        float* w2s = &hc[0][0];
        const float4* W2c = reinterpret_cast<const float4*>(W2b);
        float4* s4p = reinterpret_cast<float4*>(w2s);
        #pragma unroll
        for (int idx = tid; idx < 640; idx += 256) s4p[idx] = W2c[idx];
    }
    __syncthreads();

    const float* w2s = &hc[0][0];
    int o = tid & 15, nr = tid >> 4;
    #pragma unroll
    for (int half = 0; half < 2; half++) {
        int nn = nr + 16 * half;
        float s = __ldg(&b2b[o]);
        #pragma unroll 8
        for (int k = 0; k < 160; k++) s += h2s[nn][k] * w2s[k * 16 + o];
        int v = base + nn;
        if (v < NN) {
            g_outpre[(size_t)v * 16 + o] = s;
            atomicAdd(&sbn[o], s);
            atomicAdd(&sbnq[o], s * s);
        }
    }
    __syncthreads();
    if (tid < 16) {
        atomicAdd(&g_bnsum[tid], sbn[tid]);
        atomicAdd(&g_bnsq[tid], sbnq[tid]);
    }
}

// ---------------- BN finalize + apply + cleanup (merged; float4-vectorized zeroing) ----------------
__global__ void k_applyclean(const float* __restrict__ gamma,
                             const float* __restrict__ beta,
                             float* __restrict__ out) {
    int i = blockIdx.x * blockDim.x + threadIdx.x;
    if (i < NN * 16) {
        int o = i & 15;
        float mu = g_bnsum[o] * (1.0f / (float)NN);
        float var = g_bnsq[o] * (1.0f / (float)NN) - mu * mu;
        float rsig = rsqrtf(var + 1e-5f);
        out[i] = gamma[o] * (g_outpre[i] - mu) * rsig + beta[o];
    }
    if (i < NN * 8) {
        float4 z = make_float4(0.f, 0.f, 0.f, 0.f);
        reinterpret_cast<float4*>(g_s1)[i] = z;
        reinterpret_cast<float4*>(g_s2)[i] = z;
        reinterpret_cast<float4*>(g_s3)[i] = z;
        reinterpret_cast<float4*>(g_s4)[i] = z;
    }
    if (i < NN) { g_cnt[i] = 0; g_cursor[i] = 0; }
}

// ---------------- launch ----------------
extern "C" void kernel_launch(void* const* d_in, const int* in_sizes, int n_in,
                              void* d_out, int out_size) {
    const float* x_s       = (const float*)d_in[0];
    const float* x_t       = (const float*)d_in[1];
    const float* edge_attr = (const float*)d_in[2];
    const float* u         = (const float*)d_in[3];
    const float* W1a       = (const float*)d_in[4];
    const float* b1a       = (const float*)d_in[5];
    const float* W2a       = (const float*)d_in[6];
    const float* b2a       = (const float*)d_in[7];
    const float* W1b       = (const float*)d_in[8];
    const float* b1b       = (const float*)d_in[9];
    const float* W2b       = (const float*)d_in[10];
    const float* b2b       = (const float*)d_in[11];
    const float* gamma     = (const float*)d_in[12];
    const float* beta      = (const float*)d_in[13];
    const int*   ei        = (const int*)d_in[14];
    const int* src = ei;
    const int* tgt = ei + NE;
    float* out = (float*)d_out;

    k_inithist <<<(NE + 255) / 256, 256>>>(x_t, W1a, b1a, src);       // #1
    k_scan1    <<<NSCAN, 1024>>>();                                   // #2
    k_scatter  <<<(NE + 255) / 256, 256>>>(src, tgt);                 // #3
    k_edge     <<<NE / 256, 128>>>(edge_attr, W1a, W2a, b2a);         // #4 <- profiled slot
    k_node_mlp <<<(NN + 31) / 32, 256>>>(x_s, u, W1b, b1b, W2b, b2b); // #5
    k_applyclean<<<(NN * 16 + 255) / 256, 256>>>(gamma, beta, out);   // #6
}